// round 9
// baseline (speedup 1.0000x reference)
#include <cuda_runtime.h>
#include <cstdint>
#include <math.h>

#define BATCH 64
#define CIN   128
#define OCH   128
#define H     80
#define W     80
#define HW    6400
#define MTILE 128            // pixels per CTA
#define NCHUNK 36            // 9 taps * 4 ic-chunks of 32

// Scratch (allocation-free rule: __device__ globals)
__device__ float g_avg[BATCH * CIN * 25];                 // [b][c][5][5]
__device__ float g_dynw[(size_t)BATCH * 9 * OCH * CIN];   // [b][tap][oc][ic], tf32-rounded
__device__ float g_xt[(size_t)BATCH * HW * CIN];          // NHWC tf32-rounded copy of x

__device__ __forceinline__ uint32_t tf32r(float v) {
    uint32_t u;
    asm("cvt.rna.tf32.f32 %0, %1;" : "=r"(u) : "f"(v));
    return u;
}
__device__ __forceinline__ uint32_t smem_u32(const void* p) {
    uint32_t a;
    asm("{ .reg .u64 t; cvta.to.shared.u64 t, %1; cvt.u32.u64 %0, t; }" : "=r"(a) : "l"(p));
    return a;
}
__device__ __forceinline__ void cp_async4(uint32_t dst, const float* src, uint32_t sz) {
    asm volatile("cp.async.ca.shared.global [%0], [%1], 4, %2;"
                 :: "r"(dst), "l"(src), "r"(sz) : "memory");
}
#define CP_COMMIT() asm volatile("cp.async.commit_group;" ::: "memory")
#define CP_WAIT0()  asm volatile("cp.async.wait_group 0;" ::: "memory")

__device__ __forceinline__ void mma_tf32(float* d, const uint32_t* a, const uint32_t* bq) {
    asm volatile(
        "mma.sync.aligned.m16n8k8.row.col.f32.tf32.tf32.f32 "
        "{%0,%1,%2,%3}, {%4,%5,%6,%7}, {%8,%9}, {%0,%1,%2,%3};"
        : "+f"(d[0]), "+f"(d[1]), "+f"(d[2]), "+f"(d[3])
        : "r"(a[0]), "r"(a[1]), "r"(a[2]), "r"(a[3]), "r"(bq[0]), "r"(bq[1]));
}

// fragment-index swizzles (bijective; applied identically on store & load)
__device__ __forceinline__ int swzA(int F) {
    return F ^ ((F >> 2) & 7) ^ (((F >> 7) & 1) << 1);
}
__device__ __forceinline__ int swzB(int G) {
    return G ^ ((G >> 2) & 7) ^ (((G >> 7) & 1) << 3);
}

// ---------------------------------------------------------------------------
// Kernel T: NCHW -> NHWC transpose with tf32 pre-rounding
// block: 256 threads handle 256 pixels x 128 ic (4 passes of 32 ic)
// ---------------------------------------------------------------------------
__global__ void __launch_bounds__(256)
transform_kernel(const float* __restrict__ x) {
    __shared__ float t[32][257];
    const int tid = threadIdx.x;
    const int b   = blockIdx.y;
    const int px0 = blockIdx.x * 256;
    const float* xb  = x    + (size_t)b * CIN * HW;
    float*       xtb = g_xt + (size_t)b * HW * CIN;

    for (int pass = 0; pass < 4; pass++) {
        const int ic0 = pass * 32;
        if (pass) __syncthreads();
        #pragma unroll 4
        for (int r = 0; r < 32; r++)
            t[r][tid] = xb[(size_t)(ic0 + r) * HW + px0 + tid];
        __syncthreads();
        float* dst = xtb + (size_t)(px0 + tid) * CIN + ic0;
        #pragma unroll
        for (int q = 0; q < 8; q++) {
            float4 v;
            v.x = __uint_as_float(tf32r(t[4 * q + 0][tid]));
            v.y = __uint_as_float(tf32r(t[4 * q + 1][tid]));
            v.z = __uint_as_float(tf32r(t[4 * q + 2][tid]));
            v.w = __uint_as_float(tf32r(t[4 * q + 3][tid]));
            ((float4*)dst)[q] = v;
        }
    }
}

// ---------------------------------------------------------------------------
// Kernel A: adaptive average pool 80x80 -> 5x5 (16x16 equal tiles)
// ---------------------------------------------------------------------------
__global__ void avgpool_kernel(const float* __restrict__ x) {
    int idx = blockIdx.x * blockDim.x + threadIdx.x;
    if (idx >= BATCH * CIN * 25) return;
    int cell = idx % 25;
    int bc   = idx / 25;
    int oy = cell / 5, ox = cell % 5;
    const float* p = x + ((size_t)bc * H + oy * 16) * W + ox * 16;
    float s = 0.f;
    #pragma unroll
    for (int r = 0; r < 16; r++) {
        const float4* q = (const float4*)(p + r * W);
        #pragma unroll
        for (int j = 0; j < 4; j++) {
            float4 v = q[j];
            s += v.x + v.y + v.z + v.w;
        }
    }
    g_avg[idx] = s * (1.f / 256.f);
}

// ---------------------------------------------------------------------------
// Kernel B: attention conv (3x3 VALID on 5x5) + sigmoid + weight modulation
// Writes tf32-pre-rounded dynamic weights in layout [b][tap][oc][ic]
// ---------------------------------------------------------------------------
__global__ void att_kernel(const float* __restrict__ weight,
                           const float* __restrict__ w_att,
                           const float* __restrict__ b_att) {
    int idx = blockIdx.x * blockDim.x + threadIdx.x;   // (b*OCH + oc)*CIN + ic
    if (idx >= BATCH * OCH * CIN) return;
    int ic  = idx % CIN;
    int boc = idx / CIN;            // b*OCH + oc
    int oc  = boc % OCH;
    int b   = boc / OCH;
    int o   = oc * CIN + ic;        // attention output channel

    float a[25];
    #pragma unroll
    for (int i = 0; i < 25; i++) a[i] = g_avg[boc * 25 + i];
    float wa[9];
    #pragma unroll
    for (int i = 0; i < 9; i++) wa[i] = w_att[o * 9 + i];
    float bias = b_att[o];

    #pragma unroll
    for (int kh = 0; kh < 3; kh++) {
        #pragma unroll
        for (int kw = 0; kw < 3; kw++) {
            float s = bias;
            #pragma unroll
            for (int i = 0; i < 3; i++)
                #pragma unroll
                for (int j = 0; j < 3; j++)
                    s += a[(kh + i) * 5 + (kw + j)] * wa[i * 3 + j];
            float sig = 1.f / (1.f + expf(-s));
            int tap = kh * 3 + kw;
            float v = weight[(oc * CIN + ic) * 9 + tap] * sig;
            g_dynw[(((size_t)b * 9 + tap) * OCH + oc) * CIN + ic] = __uint_as_float(tf32r(v));
        }
    }
}

// ---------------------------------------------------------------------------
// Kernel C: tf32 mma.sync implicit-GEMM conv
// CTA: 128 pixels (M) x 128 oc (N); K = 9 taps x 128 ic in chunks of 32.
// A staged via cp.async (zfill) directly into fragment-order swizzled SMEM
// from the NHWC tf32 copy; B staged via regs + float2 STS (pre-rounded).
// Double-buffered (A0 A1 B0 B1 x 16KB), one __syncthreads per chunk.
// 8 warps: grid 2(M) x 4(N), warp tile 64x32; 2 CTAs/SM.
// ---------------------------------------------------------------------------
__global__ void __launch_bounds__(256, 2)
conv_kernel(const float* __restrict__ xt, float* __restrict__ out) {
    extern __shared__ float smem[];   // [A0 4096][A1 4096][B0 4096][B1 4096] floats

    const int tid  = threadIdx.x;
    const int lane = tid & 31, wid = tid >> 5;
    const int b    = blockIdx.y;
    const int n0   = blockIdx.x * MTILE;

    // writer identities
    const int px   = tid & 127;
    const int ih   = tid >> 7;           // 16-ic half
    const int yA   = (n0 + px) / W, xxA = (n0 + px) % W;
    const int mtw  = px >> 4;
    const int rA   = px & 15, gA = rA & 7, rhalf = rA >> 3;
    const int ocB  = tid & 127;
    const int ntw  = ocB >> 3, gB = ocB & 7;

    const float* xb    = xt + (size_t)b * HW * CIN;
    const float* wbase = g_dynw + (size_t)b * 9 * OCH * CIN;
    const uint32_t sbase = smem_u32(smem);

    // mma identities
    const int warpM = wid & 1, warpN = wid >> 1;
    const int mtb = warpM * 4, ntb = warpN * 4;

    float acc[4][4][4];
    #pragma unroll
    for (int mf = 0; mf < 4; mf++)
        #pragma unroll
        for (int nf = 0; nf < 4; nf++)
            #pragma unroll
            for (int q = 0; q < 4; q++) acc[mf][nf][q] = 0.f;

    float breg[16];

    // ---- A fill via cp.async into buf (J&1) ----
    #define FILL_A(J) do {                                                       \
        int _tap = (J) >> 2, _ic0 = ((J) & 3) * 32;                              \
        int _dy = _tap / 3 - 1, _dx = _tap % 3 - 1;                              \
        int _sy = yA + _dy, _sx = xxA + _dx;                                     \
        bool _ok = (_sy >= 0) & (_sy < H) & (_sx >= 0) & (_sx < W);              \
        int _syc = min(max(_sy, 0), H - 1), _sxc = min(max(_sx, 0), W - 1);      \
        const float* _ap = xb + (size_t)(_syc * W + _sxc) * CIN + _ic0 + ih * 16;\
        uint32_t _sz = _ok ? 4u : 0u;                                            \
        uint32_t _aB = sbase + ((J) & 1) * 16384;                                \
        _Pragma("unroll")                                                        \
        for (int ksl = 0; ksl < 2; ksl++)                                        \
            _Pragma("unroll")                                                    \
            for (int tig = 0; tig < 4; tig++) {                                  \
                int F = (mtw * 4 + ih * 2 + ksl) * 32 + gA * 4 + tig;            \
                uint32_t d0 = _aB + (uint32_t)swzA(F) * 16 + rhalf * 8;          \
                cp_async4(d0,     _ap + ksl * 8 + tig,     _sz);                 \
                cp_async4(d0 + 4, _ap + ksl * 8 + tig + 4, _sz);                 \
            }                                                                    \
    } while (0)

    // ---- B load (global -> regs) ----
    #define LOAD_B(J) do {                                                       \
        int _tap = (J) >> 2, _ic0 = ((J) & 3) * 32;                              \
        const float4* _wp = (const float4*)(wbase + ((size_t)_tap * OCH + ocB) * CIN + _ic0 + ih * 16); \
        _Pragma("unroll")                                                        \
        for (int q = 0; q < 4; q++) ((float4*)breg)[q] = __ldg(_wp + q);         \
    } while (0)

    FILL_A(0); CP_COMMIT(); LOAD_B(0);

    for (int j = 0; j < NCHUNK; j++) {
        const int buf = j & 1;
        float* sA = smem + buf * 4096;
        float* sB = smem + 8192 + buf * 4096;

        // ---- STS B(j) from regs (fragment order, swizzled) ----
        #pragma unroll
        for (int ksl = 0; ksl < 2; ksl++) {
            const int ks = ih * 2 + ksl;
            #pragma unroll
            for (int tig = 0; tig < 4; tig++) {
                int G = (ntw * 4 + ks) * 32 + gB * 4 + tig;
                float2 bv2;
                bv2.x = breg[ksl * 8 + tig];
                bv2.y = breg[ksl * 8 + tig + 4];
                *(float2*)(sB + swzB(G) * 2) = bv2;
            }
        }

        CP_WAIT0();            // A buf j complete (this thread's group)
        __syncthreads();       // all threads' A + B for buf j visible

        if (j + 1 < NCHUNK) { FILL_A(j + 1); CP_COMMIT(); LOAD_B(j + 1); }

        // ---- MMA phase: 64 mma per warp per chunk ----
        #pragma unroll
        for (int ks = 0; ks < 4; ks++) {
            uint32_t bf[4][2];
            #pragma unroll
            for (int nf = 0; nf < 4; nf++) {
                int G = ((ntb + nf) * 4 + ks) * 32 + lane;
                float2 v = *(const float2*)(sB + swzB(G) * 2);
                bf[nf][0] = __float_as_uint(v.x);
                bf[nf][1] = __float_as_uint(v.y);
            }
            #pragma unroll
            for (int mf = 0; mf < 4; mf++) {
                int F = ((mtb + mf) * 4 + ks) * 32 + lane;
                float4 a4 = *(const float4*)(sA + swzA(F) * 4);
                // layout [a0,a2,a1,a3] -> mma order (a0,a1,a2,a3)
                uint32_t av[4] = {__float_as_uint(a4.x), __float_as_uint(a4.z),
                                  __float_as_uint(a4.y), __float_as_uint(a4.w)};
                #pragma unroll
                for (int nf = 0; nf < 4; nf++)
                    mma_tf32(acc[mf][nf], av, bf[nf]);
            }
        }
    }

    // ---- epilogue: regs -> GMEM (out[b][oc][pixel]) ----
    {
        const int g = lane >> 2, tg = lane & 3;
        #pragma unroll
        for (int mf = 0; mf < 4; mf++) {
            int pix = n0 + warpM * 64 + mf * 16 + g;
            #pragma unroll
            for (int nf = 0; nf < 4; nf++) {
                int oc = warpN * 32 + nf * 8 + tg * 2;
                float* o0 = out + (size_t)(b * OCH + oc) * HW;
                o0[pix]          = acc[mf][nf][0];
                o0[HW + pix]     = acc[mf][nf][1];
                o0[pix + 8]      = acc[mf][nf][2];
                o0[HW + pix + 8] = acc[mf][nf][3];
            }
        }
    }
}

#define CONV_SMEM_BYTES (4 * 4096 * 4)   // 64 KB

// ---------------------------------------------------------------------------
extern "C" void kernel_launch(void* const* d_in, const int* in_sizes, int n_in,
                              void* d_out, int out_size) {
    const float* x      = (const float*)d_in[0];   // [64,128,80,80]
    const float* weight = (const float*)d_in[1];   // [128,128,3,3]
    const float* w_att  = (const float*)d_in[2];   // [16384,1,3,3]
    const float* b_att  = (const float*)d_in[3];   // [16384]
    float* out = (float*)d_out;                    // [64,128,80,80]

    cudaFuncSetAttribute(conv_kernel, cudaFuncAttributeMaxDynamicSharedMemorySize,
                         CONV_SMEM_BYTES);

    float* xt_dev = nullptr;
    cudaGetSymbolAddress((void**)&xt_dev, g_xt);

    {
        dim3 grid(HW / 256, BATCH);     // (25, 64)
        transform_kernel<<<grid, 256>>>(x);
    }
    {
        int ntot = BATCH * CIN * 25;
        avgpool_kernel<<<(ntot + 255) / 256, 256>>>(x);
    }
    {
        int ntot = BATCH * OCH * CIN;
        att_kernel<<<(ntot + 255) / 256, 256>>>(weight, w_att, b_att);
    }
    {
        dim3 grid(HW / MTILE, BATCH);   // (50, 64)
        conv_kernel<<<grid, 256, CONV_SMEM_BYTES>>>(xt_dev, out);
    }
}

// round 11
// speedup vs baseline: 1.4770x; 1.4770x over previous
#include <cuda_runtime.h>
#include <cstdint>
#include <math.h>

#define BATCH 64
#define CIN   128
#define OCH   128
#define H     80
#define W     80
#define HW    6400
#define MTILE 128            // pixels per CTA
#define NCHUNK 36            // 9 taps * 4 ic-chunks of 32

// Scratch (allocation-free rule: __device__ globals)
__device__ float g_avg[BATCH * CIN * 25];                 // [b][c][5][5]
__device__ float g_dynw[(size_t)BATCH * 9 * OCH * CIN];   // [b][tap][oc][ic], tf32-rounded
__device__ float g_xt[(size_t)BATCH * HW * CIN];          // NHWC tf32-rounded copy of x

__device__ __forceinline__ uint32_t tf32r(float v) {
    uint32_t u;
    asm("cvt.rna.tf32.f32 %0, %1;" : "=r"(u) : "f"(v));
    return u;
}

__device__ __forceinline__ void mma_tf32(float* d, const uint32_t* a, const uint32_t* bq) {
    asm volatile(
        "mma.sync.aligned.m16n8k8.row.col.f32.tf32.tf32.f32 "
        "{%0,%1,%2,%3}, {%4,%5,%6,%7}, {%8,%9}, {%0,%1,%2,%3};"
        : "+f"(d[0]), "+f"(d[1]), "+f"(d[2]), "+f"(d[3])
        : "r"(a[0]), "r"(a[1]), "r"(a[2]), "r"(a[3]), "r"(bq[0]), "r"(bq[1]));
}

// fragment-index swizzles (bijective; applied identically on store & load)
__device__ __forceinline__ int swzA(int F) {
    return F ^ ((F >> 2) & 7) ^ (((F >> 7) & 1) << 1);
}
__device__ __forceinline__ int swzB(int G) {
    return G ^ ((G >> 2) & 7) ^ (((G >> 7) & 1) << 3);
}

// ---------------------------------------------------------------------------
// Kernel T: NCHW -> NHWC transpose with tf32 pre-rounding
// ---------------------------------------------------------------------------
__global__ void __launch_bounds__(256)
transform_kernel(const float* __restrict__ x) {
    __shared__ float t[32][257];
    const int tid = threadIdx.x;
    const int b   = blockIdx.y;
    const int px0 = blockIdx.x * 256;
    const float* xb  = x    + (size_t)b * CIN * HW;
    float*       xtb = g_xt + (size_t)b * HW * CIN;

    for (int pass = 0; pass < 4; pass++) {
        const int ic0 = pass * 32;
        if (pass) __syncthreads();
        #pragma unroll 4
        for (int r = 0; r < 32; r++)
            t[r][tid] = xb[(size_t)(ic0 + r) * HW + px0 + tid];
        __syncthreads();
        float* dst = xtb + (size_t)(px0 + tid) * CIN + ic0;
        #pragma unroll
        for (int q = 0; q < 8; q++) {
            float4 v;
            v.x = __uint_as_float(tf32r(t[4 * q + 0][tid]));
            v.y = __uint_as_float(tf32r(t[4 * q + 1][tid]));
            v.z = __uint_as_float(tf32r(t[4 * q + 2][tid]));
            v.w = __uint_as_float(tf32r(t[4 * q + 3][tid]));
            ((float4*)dst)[q] = v;
        }
    }
}

// ---------------------------------------------------------------------------
// Kernel A: adaptive average pool 80x80 -> 5x5 (16x16 equal tiles)
// ---------------------------------------------------------------------------
__global__ void avgpool_kernel(const float* __restrict__ x) {
    int idx = blockIdx.x * blockDim.x + threadIdx.x;
    if (idx >= BATCH * CIN * 25) return;
    int cell = idx % 25;
    int bc   = idx / 25;
    int oy = cell / 5, ox = cell % 5;
    const float* p = x + ((size_t)bc * H + oy * 16) * W + ox * 16;
    float s = 0.f;
    #pragma unroll
    for (int r = 0; r < 16; r++) {
        const float4* q = (const float4*)(p + r * W);
        #pragma unroll
        for (int j = 0; j < 4; j++) {
            float4 v = q[j];
            s += v.x + v.y + v.z + v.w;
        }
    }
    g_avg[idx] = s * (1.f / 256.f);
}

// ---------------------------------------------------------------------------
// Kernel B: attention conv (3x3 VALID on 5x5) + sigmoid + weight modulation
// Writes tf32-pre-rounded dynamic weights in layout [b][tap][oc][ic]
// ---------------------------------------------------------------------------
__global__ void att_kernel(const float* __restrict__ weight,
                           const float* __restrict__ w_att,
                           const float* __restrict__ b_att) {
    int idx = blockIdx.x * blockDim.x + threadIdx.x;   // (b*OCH + oc)*CIN + ic
    if (idx >= BATCH * OCH * CIN) return;
    int ic  = idx % CIN;
    int boc = idx / CIN;            // b*OCH + oc
    int oc  = boc % OCH;
    int b   = boc / OCH;
    int o   = oc * CIN + ic;        // attention output channel

    float a[25];
    #pragma unroll
    for (int i = 0; i < 25; i++) a[i] = g_avg[boc * 25 + i];
    float wa[9];
    #pragma unroll
    for (int i = 0; i < 9; i++) wa[i] = w_att[o * 9 + i];
    float bias = b_att[o];

    #pragma unroll
    for (int kh = 0; kh < 3; kh++) {
        #pragma unroll
        for (int kw = 0; kw < 3; kw++) {
            float s = bias;
            #pragma unroll
            for (int i = 0; i < 3; i++)
                #pragma unroll
                for (int j = 0; j < 3; j++)
                    s += a[(kh + i) * 5 + (kw + j)] * wa[i * 3 + j];
            float sig = 1.f / (1.f + expf(-s));
            int tap = kh * 3 + kw;
            float v = weight[(oc * CIN + ic) * 9 + tap] * sig;
            g_dynw[(((size_t)b * 9 + tap) * OCH + oc) * CIN + ic] = __uint_as_float(tf32r(v));
        }
    }
}

// ---------------------------------------------------------------------------
// Kernel C: tf32 mma.sync implicit-GEMM conv
// CTA: 128 pixels (M) x 128 oc (N); K = 9 taps x 128 ic in chunks of 32.
// A from NHWC tf32 copy via 4x LDG.128/thread; B via 4x LDG.128/thread.
// Both staged reg -> fragment-order XOR-swizzled SMEM (conflict-free).
// Double-buffered (A0 A1 B0 B1 x 16KB), one __syncthreads per chunk.
// 8 warps: grid 2(M) x 4(N), warp tile 64x32; 2 CTAs/SM.
// ---------------------------------------------------------------------------
__global__ void __launch_bounds__(256, 2)
conv_kernel(const float* __restrict__ xt, float* __restrict__ out) {
    extern __shared__ float smem[];   // [A0 4096][A1 4096][B0 4096][B1 4096] floats

    const int tid  = threadIdx.x;
    const int lane = tid & 31, wid = tid >> 5;
    const int b    = blockIdx.y;
    const int n0   = blockIdx.x * MTILE;

    // writer identities
    const int px   = tid & 127;
    const int ih   = tid >> 7;           // 16-ic half
    const int yA   = (n0 + px) / W, xxA = (n0 + px) % W;
    const int mtw  = px >> 4;
    const int rA   = px & 15, gA = rA & 7, rhalf = rA >> 3;
    const int ocB  = tid & 127;
    const int ntw  = ocB >> 3, gB = ocB & 7;

    const float* xb    = xt + (size_t)b * HW * CIN;
    const float* wbase = g_dynw + (size_t)b * 9 * OCH * CIN;

    // mma identities
    const int warpM = wid & 1, warpN = wid >> 1;
    const int mtb = warpM * 4, ntb = warpN * 4;

    float acc[4][4][4];
    #pragma unroll
    for (int mf = 0; mf < 4; mf++)
        #pragma unroll
        for (int nf = 0; nf < 4; nf++)
            #pragma unroll
            for (int q = 0; q < 4; q++) acc[mf][nf][q] = 0.f;

    float areg[16];
    float breg[16];

    // ---- chunk loader (global -> regs); A already tf32-rounded NHWC ----
    #define LOAD_CHUNK(J) do {                                                  \
        int _tap = (J) >> 2, _ic0 = ((J) & 3) * 32;                             \
        int _dy = _tap / 3 - 1, _dx = _tap % 3 - 1;                             \
        int _sy = yA + _dy, _sx = xxA + _dx;                                    \
        bool _ok = (_sy >= 0) & (_sy < H) & (_sx >= 0) & (_sx < W);             \
        int _syc = min(max(_sy, 0), H - 1), _sxc = min(max(_sx, 0), W - 1);     \
        const float4* _ap = (const float4*)(xb + (size_t)(_syc * W + _sxc) * CIN + _ic0 + ih * 16); \
        _Pragma("unroll")                                                       \
        for (int q = 0; q < 4; q++) ((float4*)areg)[q] = __ldg(_ap + q);        \
        if (!_ok) {                                                             \
            _Pragma("unroll")                                                   \
            for (int c = 0; c < 16; c++) areg[c] = 0.f;                         \
        }                                                                       \
        const float4* _wp = (const float4*)(wbase + ((size_t)_tap * OCH + ocB) * CIN + _ic0 + ih * 16); \
        _Pragma("unroll")                                                       \
        for (int q = 0; q < 4; q++) ((float4*)breg)[q] = __ldg(_wp + q);        \
    } while (0)

    LOAD_CHUNK(0);

    for (int j = 0; j < NCHUNK; j++) {
        const int buf = j & 1;
        float* sA = smem + buf * 4096;
        float* sB = smem + 8192 + buf * 4096;

        // ---- STS: regs -> fragment-order SMEM (float2, swizzled) ----
        #pragma unroll
        for (int ksl = 0; ksl < 2; ksl++) {
            const int ks = ih * 2 + ksl;
            #pragma unroll
            for (int tig = 0; tig < 4; tig++) {
                int F = (mtw * 4 + ks) * 32 + gA * 4 + tig;
                float2 av2;
                av2.x = areg[ksl * 8 + tig];
                av2.y = areg[ksl * 8 + tig + 4];
                *(float2*)(sA + swzA(F) * 4 + rhalf * 2) = av2;
                int G = (ntw * 4 + ks) * 32 + gB * 4 + tig;
                float2 bv2;
                bv2.x = breg[ksl * 8 + tig];
                bv2.y = breg[ksl * 8 + tig + 4];
                *(float2*)(sB + swzB(G) * 2) = bv2;
            }
        }
        __syncthreads();

        if (j + 1 < NCHUNK) LOAD_CHUNK(j + 1);   // prefetch overlaps MMA below

        // ---- MMA phase: 64 mma per warp per chunk ----
        #pragma unroll
        for (int ks = 0; ks < 4; ks++) {
            uint32_t bf[4][2];
            #pragma unroll
            for (int nf = 0; nf < 4; nf++) {
                int G = ((ntb + nf) * 4 + ks) * 32 + lane;
                float2 v = *(const float2*)(sB + swzB(G) * 2);
                bf[nf][0] = __float_as_uint(v.x);
                bf[nf][1] = __float_as_uint(v.y);
            }
            #pragma unroll
            for (int mf = 0; mf < 4; mf++) {
                int F = ((mtb + mf) * 4 + ks) * 32 + lane;
                float4 a4 = *(const float4*)(smem + buf * 4096 + swzA(F) * 4);
                // layout [a0,a2,a1,a3] -> mma order (a0,a1,a2,a3)
                uint32_t av[4] = {__float_as_uint(a4.x), __float_as_uint(a4.z),
                                  __float_as_uint(a4.y), __float_as_uint(a4.w)};
                #pragma unroll
                for (int nf = 0; nf < 4; nf++)
                    mma_tf32(acc[mf][nf], av, bf[nf]);
            }
        }
    }

    // ---- epilogue: regs -> GMEM (out[b][oc][pixel]) ----
    {
        const int g = lane >> 2, tg = lane & 3;
        #pragma unroll
        for (int mf = 0; mf < 4; mf++) {
            int pix = n0 + warpM * 64 + mf * 16 + g;
            #pragma unroll
            for (int nf = 0; nf < 4; nf++) {
                int oc = warpN * 32 + nf * 8 + tg * 2;
                float* o0 = out + (size_t)(b * OCH + oc) * HW;
                o0[pix]          = acc[mf][nf][0];
                o0[HW + pix]     = acc[mf][nf][1];
                o0[pix + 8]      = acc[mf][nf][2];
                o0[HW + pix + 8] = acc[mf][nf][3];
            }
        }
    }
}

#define CONV_SMEM_BYTES (4 * 4096 * 4)   // 64 KB

// ---------------------------------------------------------------------------
extern "C" void kernel_launch(void* const* d_in, const int* in_sizes, int n_in,
                              void* d_out, int out_size) {
    const float* x      = (const float*)d_in[0];   // [64,128,80,80]
    const float* weight = (const float*)d_in[1];   // [128,128,3,3]
    const float* w_att  = (const float*)d_in[2];   // [16384,1,3,3]
    const float* b_att  = (const float*)d_in[3];   // [16384]
    float* out = (float*)d_out;                    // [64,128,80,80]

    cudaFuncSetAttribute(conv_kernel, cudaFuncAttributeMaxDynamicSharedMemorySize,
                         CONV_SMEM_BYTES);

    float* xt_dev = nullptr;
    cudaGetSymbolAddress((void**)&xt_dev, g_xt);

    {
        dim3 grid(HW / 256, BATCH);     // (25, 64)
        transform_kernel<<<grid, 256>>>(x);
    }
    {
        int ntot = BATCH * CIN * 25;
        avgpool_kernel<<<(ntot + 255) / 256, 256>>>(x);
    }
    {
        int ntot = BATCH * OCH * CIN;
        att_kernel<<<(ntot + 255) / 256, 256>>>(weight, w_att, b_att);
    }
    {
        dim3 grid(HW / MTILE, BATCH);   // (50, 64)
        conv_kernel<<<grid, 256, CONV_SMEM_BYTES>>>(xt_dev, out);
    }
}

// round 12
// speedup vs baseline: 1.9072x; 1.2913x over previous
#include <cuda_runtime.h>
#include <cstdint>
#include <math.h>

#define BATCH 64
#define CIN   128
#define OCH   128
#define H     80
#define W     80
#define HW    6400
#define MTILE 128            // pixels per CTA
#define NCHUNK 36            // 9 taps * 4 ic-chunks of 32

// Scratch (allocation-free rule: __device__ globals)
__device__ float g_avg[BATCH * CIN * 25];                 // [b][c][5][5]
__device__ float g_dynw[(size_t)BATCH * 9 * OCH * CIN];   // [b][tap][oc][ic], tf32-rounded
__device__ float g_xt[(size_t)BATCH * HW * CIN];          // NHWC tf32-rounded copy of x

__device__ __forceinline__ uint32_t tf32r(float v) {
    uint32_t u;
    asm("cvt.rna.tf32.f32 %0, %1;" : "=r"(u) : "f"(v));
    return u;
}

__device__ __forceinline__ void mma_tf32(float* d, const uint32_t* a, const uint32_t* bq) {
    asm volatile(
        "mma.sync.aligned.m16n8k8.row.col.f32.tf32.tf32.f32 "
        "{%0,%1,%2,%3}, {%4,%5,%6,%7}, {%8,%9}, {%0,%1,%2,%3};"
        : "+f"(d[0]), "+f"(d[1]), "+f"(d[2]), "+f"(d[3])
        : "r"(a[0]), "r"(a[1]), "r"(a[2]), "r"(a[3]), "r"(bq[0]), "r"(bq[1]));
}

// fragment-index swizzles (bijective; applied identically on store & load)
__device__ __forceinline__ int swzA(int F) {
    return F ^ ((F >> 2) & 7) ^ (((F >> 7) & 1) << 1);
}
__device__ __forceinline__ int swzB(int G) {
    return G ^ ((G >> 2) & 7) ^ (((G >> 7) & 1) << 3);
}

// ---------------------------------------------------------------------------
// Kernel T: NCHW -> NHWC transpose with tf32 pre-rounding
// ---------------------------------------------------------------------------
__global__ void __launch_bounds__(256)
transform_kernel(const float* __restrict__ x) {
    __shared__ float t[32][257];
    const int tid = threadIdx.x;
    const int b   = blockIdx.y;
    const int px0 = blockIdx.x * 256;
    const float* xb  = x    + (size_t)b * CIN * HW;
    float*       xtb = g_xt + (size_t)b * HW * CIN;

    for (int pass = 0; pass < 4; pass++) {
        const int ic0 = pass * 32;
        if (pass) __syncthreads();
        #pragma unroll 4
        for (int r = 0; r < 32; r++)
            t[r][tid] = xb[(size_t)(ic0 + r) * HW + px0 + tid];
        __syncthreads();
        float* dst = xtb + (size_t)(px0 + tid) * CIN + ic0;
        #pragma unroll
        for (int q = 0; q < 8; q++) {
            float4 v;
            v.x = __uint_as_float(tf32r(t[4 * q + 0][tid]));
            v.y = __uint_as_float(tf32r(t[4 * q + 1][tid]));
            v.z = __uint_as_float(tf32r(t[4 * q + 2][tid]));
            v.w = __uint_as_float(tf32r(t[4 * q + 3][tid]));
            ((float4*)dst)[q] = v;
        }
    }
}

// ---------------------------------------------------------------------------
// Kernel A: adaptive average pool 80x80 -> 5x5 (16x16 equal tiles)
// ---------------------------------------------------------------------------
__global__ void avgpool_kernel(const float* __restrict__ x) {
    int idx = blockIdx.x * blockDim.x + threadIdx.x;
    if (idx >= BATCH * CIN * 25) return;
    int cell = idx % 25;
    int bc   = idx / 25;
    int oy = cell / 5, ox = cell % 5;
    const float* p = x + ((size_t)bc * H + oy * 16) * W + ox * 16;
    float s = 0.f;
    #pragma unroll
    for (int r = 0; r < 16; r++) {
        const float4* q = (const float4*)(p + r * W);
        #pragma unroll
        for (int j = 0; j < 4; j++) {
            float4 v = q[j];
            s += v.x + v.y + v.z + v.w;
        }
    }
    g_avg[idx] = s * (1.f / 256.f);
}

// ---------------------------------------------------------------------------
// Kernel B: attention conv (3x3 VALID on 5x5) + sigmoid + weight modulation
// Writes tf32-pre-rounded dynamic weights in layout [b][tap][oc][ic]
// ---------------------------------------------------------------------------
__global__ void att_kernel(const float* __restrict__ weight,
                           const float* __restrict__ w_att,
                           const float* __restrict__ b_att) {
    int idx = blockIdx.x * blockDim.x + threadIdx.x;   // (b*OCH + oc)*CIN + ic
    if (idx >= BATCH * OCH * CIN) return;
    int ic  = idx % CIN;
    int boc = idx / CIN;            // b*OCH + oc
    int oc  = boc % OCH;
    int b   = boc / OCH;
    int o   = oc * CIN + ic;        // attention output channel

    float a[25];
    #pragma unroll
    for (int i = 0; i < 25; i++) a[i] = g_avg[boc * 25 + i];
    float wa[9];
    #pragma unroll
    for (int i = 0; i < 9; i++) wa[i] = w_att[o * 9 + i];
    float bias = b_att[o];

    #pragma unroll
    for (int kh = 0; kh < 3; kh++) {
        #pragma unroll
        for (int kw = 0; kw < 3; kw++) {
            float s = bias;
            #pragma unroll
            for (int i = 0; i < 3; i++)
                #pragma unroll
                for (int j = 0; j < 3; j++)
                    s += a[(kh + i) * 5 + (kw + j)] * wa[i * 3 + j];
            float sig = 1.f / (1.f + expf(-s));
            int tap = kh * 3 + kw;
            float v = weight[(oc * CIN + ic) * 9 + tap] * sig;
            g_dynw[(((size_t)b * 9 + tap) * OCH + oc) * CIN + ic] = __uint_as_float(tf32r(v));
        }
    }
}

// ---------------------------------------------------------------------------
// Kernel C: tf32 mma.sync implicit-GEMM conv  (R7 structure + NHWC A path)
// CTA: 128 pixels (M) x 128 oc (N); K = 9 taps x 128 ic in chunks of 32.
// A from NHWC tf32 copy via 4x LDG.128/thread (no cvt in hot loop);
// B via 4x LDG.128/thread (pre-rounded). Both staged reg -> fragment-order
// XOR-swizzled SMEM (conflict-free STS/LDS). Double-buffered, 1 sync/chunk.
// 8 warps: grid 2(M) x 4(N), warp tile 64x32. Natural regs (1 CTA/SM).
// ---------------------------------------------------------------------------
__global__ void __launch_bounds__(256)
conv_kernel(const float* __restrict__ xt, float* __restrict__ out) {
    extern __shared__ float smem[];   // [A0 4096][A1 4096][B0 4096][B1 4096] floats

    const int tid  = threadIdx.x;
    const int lane = tid & 31, wid = tid >> 5;
    const int b    = blockIdx.y;
    const int n0   = blockIdx.x * MTILE;

    // writer identities
    const int px   = tid & 127;
    const int ih   = tid >> 7;           // 16-ic half
    const int yA   = (n0 + px) / W, xxA = (n0 + px) % W;
    const int mtw  = px >> 4;
    const int rA   = px & 15, gA = rA & 7, rhalf = rA >> 3;
    const int ocB  = tid & 127;
    const int ntw  = ocB >> 3, gB = ocB & 7;

    const float* xb    = xt + (size_t)b * HW * CIN;
    const float* wbase = g_dynw + (size_t)b * 9 * OCH * CIN;

    // mma identities
    const int warpM = wid & 1, warpN = wid >> 1;
    const int mtb = warpM * 4, ntb = warpN * 4;

    float acc[4][4][4];
    #pragma unroll
    for (int mf = 0; mf < 4; mf++)
        #pragma unroll
        for (int nf = 0; nf < 4; nf++)
            #pragma unroll
            for (int q = 0; q < 4; q++) acc[mf][nf][q] = 0.f;

    float areg[16];
    float breg[16];

    // ---- chunk loader (global -> regs); A pre-rounded NHWC, contiguous ----
    #define LOAD_CHUNK(J) do {                                                  \
        int _tap = (J) >> 2, _ic0 = ((J) & 3) * 32;                             \
        int _dy = _tap / 3 - 1, _dx = _tap % 3 - 1;                             \
        int _sy = yA + _dy, _sx = xxA + _dx;                                    \
        bool _ok = (_sy >= 0) & (_sy < H) & (_sx >= 0) & (_sx < W);             \
        int _syc = min(max(_sy, 0), H - 1), _sxc = min(max(_sx, 0), W - 1);     \
        const float4* _ap = (const float4*)(xb + (size_t)(_syc * W + _sxc) * CIN + _ic0 + ih * 16); \
        _Pragma("unroll")                                                       \
        for (int q = 0; q < 4; q++) ((float4*)areg)[q] = __ldg(_ap + q);        \
        if (!_ok) {                                                             \
            _Pragma("unroll")                                                   \
            for (int c = 0; c < 16; c++) areg[c] = 0.f;                         \
        }                                                                       \
        const float4* _wp = (const float4*)(wbase + ((size_t)_tap * OCH + ocB) * CIN + _ic0 + ih * 16); \
        _Pragma("unroll")                                                       \
        for (int q = 0; q < 4; q++) ((float4*)breg)[q] = __ldg(_wp + q);        \
    } while (0)

    LOAD_CHUNK(0);

    for (int j = 0; j < NCHUNK; j++) {
        const int buf = j & 1;
        float* sA = smem + buf * 4096;
        float* sB = smem + 8192 + buf * 4096;

        // ---- STS: regs -> fragment-order SMEM (float2, swizzled) ----
        #pragma unroll
        for (int ksl = 0; ksl < 2; ksl++) {
            const int ks = ih * 2 + ksl;
            #pragma unroll
            for (int tig = 0; tig < 4; tig++) {
                int F = (mtw * 4 + ks) * 32 + gA * 4 + tig;
                float2 av2;
                av2.x = areg[ksl * 8 + tig];
                av2.y = areg[ksl * 8 + tig + 4];
                *(float2*)(sA + swzA(F) * 4 + rhalf * 2) = av2;
                int G = (ntw * 4 + ks) * 32 + gB * 4 + tig;
                float2 bv2;
                bv2.x = breg[ksl * 8 + tig];
                bv2.y = breg[ksl * 8 + tig + 4];
                *(float2*)(sB + swzB(G) * 2) = bv2;
            }
        }
        __syncthreads();

        if (j + 1 < NCHUNK) LOAD_CHUNK(j + 1);   // prefetch overlaps MMA below

        // ---- MMA phase: 64 mma per warp per chunk ----
        #pragma unroll
        for (int ks = 0; ks < 4; ks++) {
            uint32_t bf[4][2];
            #pragma unroll
            for (int nf = 0; nf < 4; nf++) {
                int G = ((ntb + nf) * 4 + ks) * 32 + lane;
                float2 v = *(const float2*)(sB + swzB(G) * 2);
                bf[nf][0] = __float_as_uint(v.x);
                bf[nf][1] = __float_as_uint(v.y);
            }
            #pragma unroll
            for (int mf = 0; mf < 4; mf++) {
                int F = ((mtb + mf) * 4 + ks) * 32 + lane;
                float4 a4 = *(const float4*)(sA + swzA(F) * 4);
                // layout [a0,a2,a1,a3] -> mma order (a0,a1,a2,a3)
                uint32_t av[4] = {__float_as_uint(a4.x), __float_as_uint(a4.z),
                                  __float_as_uint(a4.y), __float_as_uint(a4.w)};
                #pragma unroll
                for (int nf = 0; nf < 4; nf++)
                    mma_tf32(acc[mf][nf], av, bf[nf]);
            }
        }
    }

    // ---- epilogue: regs -> GMEM (out[b][oc][pixel]) ----
    {
        const int g = lane >> 2, tg = lane & 3;
        #pragma unroll
        for (int mf = 0; mf < 4; mf++) {
            int pix = n0 + warpM * 64 + mf * 16 + g;
            #pragma unroll
            for (int nf = 0; nf < 4; nf++) {
                int oc = warpN * 32 + nf * 8 + tg * 2;
                float* o0 = out + (size_t)(b * OCH + oc) * HW;
                o0[pix]          = acc[mf][nf][0];
                o0[HW + pix]     = acc[mf][nf][1];
                o0[pix + 8]      = acc[mf][nf][2];
                o0[HW + pix + 8] = acc[mf][nf][3];
            }
        }
    }
}

#define CONV_SMEM_BYTES (4 * 4096 * 4)   // 64 KB

// ---------------------------------------------------------------------------
extern "C" void kernel_launch(void* const* d_in, const int* in_sizes, int n_in,
                              void* d_out, int out_size) {
    const float* x      = (const float*)d_in[0];   // [64,128,80,80]
    const float* weight = (const float*)d_in[1];   // [128,128,3,3]
    const float* w_att  = (const float*)d_in[2];   // [16384,1,3,3]
    const float* b_att  = (const float*)d_in[3];   // [16384]
    float* out = (float*)d_out;                    // [64,128,80,80]

    cudaFuncSetAttribute(conv_kernel, cudaFuncAttributeMaxDynamicSharedMemorySize,
                         CONV_SMEM_BYTES);

    float* xt_dev = nullptr;
    cudaGetSymbolAddress((void**)&xt_dev, g_xt);

    {
        dim3 grid(HW / 256, BATCH);     // (25, 64)
        transform_kernel<<<grid, 256>>>(x);
    }
    {
        int ntot = BATCH * CIN * 25;
        avgpool_kernel<<<(ntot + 255) / 256, 256>>>(x);
    }
    {
        int ntot = BATCH * OCH * CIN;
        att_kernel<<<(ntot + 255) / 256, 256>>>(weight, w_att, b_att);
    }
    {
        dim3 grid(HW / MTILE, BATCH);   // (50, 64)
        conv_kernel<<<grid, 256, CONV_SMEM_BYTES>>>(xt_dev, out);
    }
}